// round 10
// baseline (speedup 1.0000x reference)
#include <cuda_runtime.h>
#include <cstdint>

// Causal muP attention (scale=1/dhead), B=2 H=16 L=2048 D=64, fp32 in/out.
// FA2 + mma.sync.m16n8k8 TF32.
// R10: 256-thread CTA, 8 warps x 16 q-rows, BN=32, Q fragments in REGISTERS
//      (no Q smem, no per-tile A-fragment LDS), regs <= 128 => 2 CTA/SM
//      = 16 warps/SM. Fixed-max softmax (muP), double-buffered K/V.

#define BM 128
#define BN 32
#define DD 64
#define NTHREADS 256

#define KF_FLOATS 2048           // per buffer: [kt 8][p 2][ln^kt][odd*2+reg]
#define VF_FLOATS 2048           // per buffer: [ktp 4][pd 4][ln^pd][odd*2+regv]
#define SMEM_FLOATS (2*KF_FLOATS + 2*VF_FLOATS)
#define SMEM_BYTES (SMEM_FLOATS * 4)     // 32768

__device__ __forceinline__ uint32_t f2tf(float f) {
    uint32_t r;
    asm("cvt.rna.tf32.f32 %0, %1;" : "=r"(r) : "f"(f));
    return r;
}
__device__ __forceinline__ float ex2(float x) {
    float y;
    asm("ex2.approx.f32 %0, %1;" : "=f"(y) : "f"(x));
    return y;
}
__device__ __forceinline__ void mma_tf32(float* d,
                                         uint32_t a0, uint32_t a1, uint32_t a2, uint32_t a3,
                                         uint32_t b0, uint32_t b1) {
    asm volatile(
        "mma.sync.aligned.m16n8k8.row.col.f32.tf32.tf32.f32 "
        "{%0,%1,%2,%3}, {%4,%5,%6,%7}, {%8,%9}, {%0,%1,%2,%3};"
        : "+f"(d[0]), "+f"(d[1]), "+f"(d[2]), "+f"(d[3])
        : "r"(a0), "r"(a1), "r"(a2), "r"(a3), "r"(b0), "r"(b1));
}

// K tile scatter (32 kv x 64 d), 256 threads, raw fp32, word = odd*2+reg.
// kr[t] = K[(tid>>4) + 16t][d4..d4+3], t = 0..1.
__device__ __forceinline__ void scatter_k(float* Kc, const float4* kr, int tid) {
    const int d4  = (tid & 15) * 4;
    const int kt  = d4 >> 3;
    const int reg = (d4 >> 2) & 1;
    #pragma unroll
    for (int t = 0; t < 2; t++) {
        const int n     = (tid >> 4) + t * 16;       // 0..31
        const int nt    = n >> 3;                    // 0..3
        const int local = n & 7;
        const int slot  = (local < 4) ? (2 * local) : (2 * local - 7);
        const int p     = nt >> 1;
        const int odd   = nt & 1;
        const float v[4] = {kr[t].x, kr[t].y, kr[t].z, kr[t].w};
        #pragma unroll
        for (int e = 0; e < 4; e++) {
            int ln  = (slot * 4 + e) ^ kt;           // swizzle (cancels on read)
            int idx = ((kt * 2 + p) * 32 + ln) * 4 + odd * 2 + reg;
            Kc[idx] = v[e];
        }
    }
}
// V tile scatter (32 kv x 64 d), 256 threads, raw fp32.
// vr[t] = V[(tid>>4) + 16t][d4..d4+3], t = 0..1.
__device__ __forceinline__ void scatter_v(float* Vc, const float4* vr, int tid) {
    const int d4  = (tid & 15) * 4;
    const int dt  = d4 >> 3;
    const int pd  = dt >> 1;
    const int odd = dt & 1;
    #pragma unroll
    for (int t = 0; t < 2; t++) {
        const int n    = (tid >> 4) + t * 16;        // 0..31
        const int ktp  = n >> 3;                     // 0..3
        const int regv = (n >> 2) & 1;
        const int ll   = n & 3;
        const float v[4] = {vr[t].x, vr[t].y, vr[t].z, vr[t].w};
        #pragma unroll
        for (int e = 0; e < 4; e++) {
            int ln  = (((d4 & 7) + e) * 4 + ll) ^ pd;    // swizzle
            int idx = ((ktp * 4 + pd) * 32 + ln) * 4 + odd * 2 + regv;
            Vc[idx] = v[e];
        }
    }
}

__global__ __launch_bounds__(NTHREADS, 2)
void fa_tc_kernel(const float* __restrict__ Q, const float* __restrict__ K,
                  const float* __restrict__ V, float* __restrict__ O, int L)
{
    extern __shared__ float sm[];
    float* Kf0 = sm;
    float* Kf1 = Kf0 + KF_FLOATS;
    float* Vf0 = Kf1 + KF_FLOATS;
    float* Vf1 = Vf0 + VF_FLOATS;
    float* Kbuf[2] = {Kf0, Kf1};
    float* Vbuf[2] = {Vf0, Vf1};

    const int qi    = (gridDim.x - 1) - blockIdx.x;   // heavy tiles first
    const int bh    = blockIdx.y;
    const int qbase = qi * BM;
    const float qscale = 1.4426950408889634f / 64.0f; // log2(e)/dhead

    const int tid  = threadIdx.x;
    const int w    = tid >> 5;      // warp 0..7, owns rows [w*16, w*16+16)
    const int lane = tid & 31;

    const float* Qg = Q + (size_t)bh * L * DD;
    const float* Kg = K + (size_t)bh * L * DD;
    const float* Vg = V + (size_t)bh * L * DD;
    float*       Og = O + (size_t)bh * L * DD;

    // ---- Q A-fragments directly into registers (loaded once) ----
    // reg0:(r,c) reg1:(r+8,c) reg2:(r,c+4) reg3:(r+8,c+4); r=lane>>2, c=lane&3
    uint32_t q[8][4];
    {
        const int rA = qbase + w * 16 + (lane >> 2);
        const int c  = lane & 3;
        const float* qa = Qg + (size_t)rA * DD;
        const float* qb = Qg + (size_t)(rA + 8) * DD;
        #pragma unroll
        for (int kt = 0; kt < 8; kt++) {
            q[kt][0] = f2tf(qa[kt * 8 + c]     * qscale);
            q[kt][1] = f2tf(qb[kt * 8 + c]     * qscale);
            q[kt][2] = f2tf(qa[kt * 8 + c + 4] * qscale);
            q[kt][3] = f2tf(qb[kt * 8 + c + 4] * qscale);
        }
    }

    // ---- prologue: tile 0 into buffer 0 ----
    {
        float4 kr[2], vr[2];
        #pragma unroll
        for (int t = 0; t < 2; t++) {
            int n = (tid >> 4) + t * 16;
            kr[t] = *(const float4*)(Kg + (size_t)n * DD + (tid & 15) * 4);
            vr[t] = *(const float4*)(Vg + (size_t)n * DD + (tid & 15) * 4);
        }
        scatter_k(Kf0, kr, tid);
        scatter_v(Vf0, vr, tid);
    }
    __syncthreads();

    float s[4][4], o[8][4];
    float lA = 0.0f, lB = 0.0f;
    #pragma unroll
    for (int dt = 0; dt < 8; dt++)
        #pragma unroll
        for (int j = 0; j < 4; j++) o[dt][j] = 0.0f;

    const int wrow0 = qbase + w * 16;
    const int njt   = 4 * qi + 4;

    for (int jt = 0; jt < njt; jt++) {
        const int   cur       = jt & 1;
        const bool  have_next = (jt + 1 < njt);
        const int   kbase     = jt * BN;
        const bool  active    = (kbase <= wrow0 + 15);
        const float* Kc = Kbuf[cur];
        const float* Vc = Vbuf[cur];

        // prefetch next K tile (latency hidden under GEMM1)
        float4 kr[2];
        if (have_next) {
            const float* Kn = Kg + (size_t)(kbase + BN) * DD;
            #pragma unroll
            for (int t = 0; t < 2; t++)
                kr[t] = *(const float4*)(Kn + ((tid >> 4) + t * 16) * DD + (tid & 15) * 4);
        }

        // ---- GEMM1: S = Q K^T (A from registers, B from smem) ----
        if (active) {
            #pragma unroll
            for (int nt = 0; nt < 4; nt++)
                #pragma unroll
                for (int j = 0; j < 4; j++) s[nt][j] = 0.0f;
            #pragma unroll
            for (int kt = 0; kt < 8; kt++) {
                #pragma unroll
                for (int p = 0; p < 2; p++) {
                    uint4 b = *(const uint4*)&Kc[((kt * 2 + p) * 32 + (lane ^ kt)) * 4];
                    mma_tf32(s[2 * p],     q[kt][0], q[kt][1], q[kt][2], q[kt][3], b.x, b.y);
                    mma_tf32(s[2 * p + 1], q[kt][0], q[kt][1], q[kt][2], q[kt][3], b.z, b.w);
                }
            }
        }

        // store next K; prefetch next V
        float4 vr[2];
        if (have_next) {
            scatter_k(Kbuf[cur ^ 1], kr, tid);
            const float* Vn = Vg + (size_t)(kbase + BN) * DD;
            #pragma unroll
            for (int t = 0; t < 2; t++)
                vr[t] = *(const float4*)(Vn + ((tid >> 4) + t * 16) * DD + (tid & 15) * 4);
        }

        if (active) {
            // ---- causal mask (perm-aware: c0<->kv c, c1<->kv c+4) ----
            if (kbase + BN - 1 > wrow0) {
                int rA = wrow0 + (lane >> 2);
                int rB = rA + 8;
                #pragma unroll
                for (int nt = 0; nt < 4; nt++) {
                    int col = kbase + nt * 8 + (lane & 3);
                    if (col     > rA) s[nt][0] = -1e30f;
                    if (col + 4 > rA) s[nt][1] = -1e30f;
                    if (col     > rB) s[nt][2] = -1e30f;
                    if (col + 4 > rB) s[nt][3] = -1e30f;
                }
            }
            // ---- softmax numerator, fixed max=0 (muP: |s| << 1) ----
            float sumA = 0.0f, sumB = 0.0f;
            #pragma unroll
            for (int nt = 0; nt < 4; nt++) {
                float p0 = ex2(s[nt][0]);
                float p1 = ex2(s[nt][1]);
                float p2 = ex2(s[nt][2]);
                float p3 = ex2(s[nt][3]);
                sumA += p0 + p1;
                sumB += p2 + p3;
                s[nt][0] = p0;
                s[nt][1] = p1;
                s[nt][2] = p2;
                s[nt][3] = p3;
            }
            lA += sumA;
            lB += sumB;
            // ---- GEMM2: O += P V (P = s regs, order {0,2,1,3}) ----
            #pragma unroll
            for (int ktp = 0; ktp < 4; ktp++) {
                uint32_t p0 = __float_as_uint(s[ktp][0]);
                uint32_t p1 = __float_as_uint(s[ktp][2]);
                uint32_t p2 = __float_as_uint(s[ktp][1]);
                uint32_t p3 = __float_as_uint(s[ktp][3]);
                #pragma unroll
                for (int pd = 0; pd < 4; pd++) {
                    uint4 b = *(const uint4*)&Vc[((ktp * 4 + pd) * 32 + (lane ^ pd)) * 4];
                    mma_tf32(o[2 * pd],     p0, p1, p2, p3, b.x, b.y);
                    mma_tf32(o[2 * pd + 1], p0, p1, p2, p3, b.z, b.w);
                }
            }
        }

        if (have_next) {
            scatter_v(Vbuf[cur ^ 1], vr, tid);
            __syncthreads();
        }
    }

    // ---- epilogue: reduce l across quad, normalize, store ----
    lA += __shfl_xor_sync(0xffffffffu, lA, 1);
    lA += __shfl_xor_sync(0xffffffffu, lA, 2);
    lB += __shfl_xor_sync(0xffffffffu, lB, 1);
    lB += __shfl_xor_sync(0xffffffffu, lB, 2);
    float invA = 1.0f / lA;
    float invB = 1.0f / lB;

    int rA = qbase + w * 16 + (lane >> 2);
    int rB = rA + 8;
    #pragma unroll
    for (int dt = 0; dt < 8; dt++) {
        int d0 = dt * 8 + 2 * (lane & 3);
        float2 oa = make_float2(o[dt][0] * invA, o[dt][1] * invA);
        float2 ob = make_float2(o[dt][2] * invB, o[dt][3] * invB);
        *(float2*)(Og + (size_t)rA * DD + d0) = oa;
        *(float2*)(Og + (size_t)rB * DD + d0) = ob;
    }
}

extern "C" void kernel_launch(void* const* d_in, const int* in_sizes, int n_in,
                              void* d_out, int out_size)
{
    const float* Q = (const float*)d_in[0];
    const float* K = (const float*)d_in[1];
    const float* V = (const float*)d_in[2];
    float* O = (float*)d_out;

    const int L = 2048;

    cudaFuncSetAttribute(fa_tc_kernel,
                         cudaFuncAttributeMaxDynamicSharedMemorySize, SMEM_BYTES);

    dim3 grid(L / BM, 32);    // (16, 32)
    fa_tc_kernel<<<grid, NTHREADS, SMEM_BYTES>>>(Q, K, V, O, L);
}